// round 1
// baseline (speedup 1.0000x reference)
#include <cuda_runtime.h>
#include <math.h>

#define Bb 8
#define Cc 16
#define WD 192
#define HT 192
#define NPIX (WD*HT)
#define Hh 4
#define HID 16
#define OCH 32
#define W2 214
#define SDIM 144

// ---------------- device scratch (no allocations allowed) ----------------
__device__ float g_Wq[Hh][HID][SDIM];
__device__ float g_Wk[Hh][128][SDIM];
__device__ float g_Wv[Hh][128][SDIM];
__device__ float g_S[Bb*Hh][SDIM*SDIM];
__device__ float g_W2[Bb][Hh][OCH][SDIM];
__device__ float g_bnsum[OCH];
__device__ float g_bnsq[OCH];

__constant__ int c_shift[4] = {1, 2, 4, 8};
__constant__ int c_off[8]   = {0, 1, 2, 5, 8, 7, 6, 3}; // position of the -1 tap per contrast kernel

// ---------------- kernel 1: fold blend kernels into effective conv weights ----------------
__global__ void k_prep(const float* __restrict__ wq, const float* __restrict__ wk,
                       const float* __restrict__ wv, const float* __restrict__ sum_w) {
    int h = blockIdx.x;
    int t = threadIdx.x;
    __shared__ float wcen[Cc][9];
    __shared__ float wsur[Cc][8][9];

    if (t < Cc * 9) {
        int c = t / 9, d = t % 9;
        float sw = sum_w[h * Cc + c];
        float su_f = (d == 4) ? 0.125f : (7.0f / 64.0f);
        float ce   = (d == 4) ? 1.0f : 0.0f;
        wcen[c][d] = su_f * (1.0f - sw) + ce * sw;
    }
    for (int idx = t; idx < Cc * 8 * 9; idx += 256) {
        int c = idx / 72;
        int k = (idx / 9) % 8;
        int d = idx % 9;
        float sw = sum_w[h * Cc + c];
        float delta = ((d == 4) ? 1.0f : 0.0f) + ((d == c_off[k]) ? -1.0f : 0.0f);
        float ce    = (d == 4) ? 1.0f : 0.0f;
        float k2w   = (delta - ce) * 1.125f + 0.125f;
        wsur[c][k][d] = delta * (1.0f - sw) + k2w * sw;
    }
    __syncthreads();

    for (int idx = t; idx < HID * SDIM; idx += 256) {
        int q = idx / SDIM, c = (idx % SDIM) / 9, d = idx % 9;
        g_Wq[h][q][c * 9 + d] = wq[(h * HID + q) * Cc + c] * wcen[c][d];
    }
    for (int idx = t; idx < 128 * SDIM; idx += 256) {
        int o = idx / SDIM, c = (idx % SDIM) / 9, d = idx % 9;
        float ak = 0.0f, av = 0.0f;
        #pragma unroll
        for (int k = 0; k < 8; k++) {
            float ws = wsur[c][k][d];
            ak = fmaf(wk[(h * 128 + o) * 128 + k * Cc + c], ws, ak);
            av = fmaf(wv[(h * 128 + o) * 128 + k * Cc + c], ws, av);
        }
        g_Wk[h][o][c * 9 + d] = ak;
        g_Wv[h][o][c * 9 + d] = av;
    }
}

// ---------------- kernel 2: zero scratch accumulators ----------------
__global__ void k_zero() {
    long total = (long)Bb * Hh * SDIM * SDIM;
    float* p = &g_S[0][0];
    for (long i = (long)blockIdx.x * 256 + threadIdx.x; i < total; i += (long)gridDim.x * 256)
        p[i] = 0.0f;
    if (blockIdx.x == 0 && threadIdx.x < OCH) {
        g_bnsum[threadIdx.x] = 0.0f;
        g_bnsq[threadIdx.x]  = 0.0f;
    }
}

// ---------------- kernel 3: S = X X^T  (144x144 per (b,h)) ----------------
// grid (24 x-groups of 8 rows, Hh, Bb), 256 threads as 16x16, each computes a 9x9 tile of S.
__global__ void __launch_bounds__(256, 2) k_S(const float* __restrict__ cen) {
    __shared__ float sm[Cc * 3 * W2];
    int xg = blockIdx.x, h = blockIdx.y, b = blockIdx.z;
    int s = c_shift[h];
    int t = threadIdx.x, ti = t & 15, tj = t >> 4;

    float acc[81];
    #pragma unroll
    for (int i = 0; i < 81; i++) acc[i] = 0.0f;

    const float* cb = cen + (size_t)b * Cc * NPIX;
    int plen = HT + 2 * s;

    for (int xr = 0; xr < 8; xr++) {
        int x = xg * 8 + xr;
        __syncthreads();
        for (int idx = t; idx < Cc * 3 * plen; idx += 256) {
            int c = idx / (3 * plen);
            int rem = idx - c * 3 * plen;
            int r = rem / plen;
            int p = rem - r * plen;
            int xx = x + (r - 1) * s;
            int y = p - s;
            float v = 0.0f;
            if (xx >= 0 && xx < WD && y >= 0 && y < HT)
                v = cb[((size_t)c * WD + xx) * HT + y];
            sm[c * (3 * W2) + r * W2 + p] = v;
        }
        __syncthreads();

        const float* pa = sm + ti * (3 * W2);
        const float* pb = sm + tj * (3 * W2);
        #pragma unroll 4
        for (int y = 0; y < HT; y++) {
            float a[9], bbv[9];
            #pragma unroll
            for (int i = 0; i < 9; i++) a[i] = pa[(i / 3) * W2 + (i % 3) * s + y];
            #pragma unroll
            for (int j = 0; j < 9; j++) bbv[j] = pb[(j / 3) * W2 + (j % 3) * s + y];
            #pragma unroll
            for (int i = 0; i < 9; i++)
                #pragma unroll
                for (int j = 0; j < 9; j++)
                    acc[i * 9 + j] = fmaf(a[i], bbv[j], acc[i * 9 + j]);
        }
    }

    float* Sg = g_S[b * Hh + h];
    #pragma unroll
    for (int i = 0; i < 9; i++)
        #pragma unroll
        for (int j = 0; j < 9; j++)
            atomicAdd(&Sg[(ti * 9 + i) * SDIM + (tj * 9 + j)], acc[i * 9 + j]);
}

// ---------------- kernel 4: per (b,h) attention head from S ----------------
// G = Wq S Wk^T, norms, score, instance norm, softmax, M = w_out*attn, Weff2 = M*Wv
__global__ void __launch_bounds__(256) k_attn(const float* __restrict__ w_out) {
    __shared__ float pool[8976];
    __shared__ float nq[16], nk[128], red[256];
    float* Wq_sm = pool;           // [0,2304)
    float* stage = pool + 2304;    // [2304,4624)  16 rows x 145
    float* Tt    = pool + 4624;    // [4624,6928)
    float* G     = pool + 6928;    // [6928,8976)
    float* M     = pool;           // overlay (4096), used after Wq/stage are done

    int bh = blockIdx.x;
    int b = bh >> 2, h = bh & 3;
    int t = threadIdx.x;
    const float* Sg = g_S[bh];

    for (int idx = t; idx < 16 * SDIM; idx += 256)
        Wq_sm[idx] = (&g_Wq[h][0][0])[idx];
    __syncthreads();

    // T = Wq * S
    for (int idx = t; idx < 16 * SDIM; idx += 256) {
        int q = idx / SDIM, i = idx - q * SDIM;
        float a = 0.0f;
        for (int j = 0; j < SDIM; j++)
            a = fmaf(Wq_sm[q * SDIM + j], Sg[j * SDIM + i], a);
        Tt[idx] = a;
    }
    __syncthreads();

    if (t < 16) {
        float a = 0.0f;
        for (int i = 0; i < SDIM; i++)
            a = fmaf(Tt[t * SDIM + i], Wq_sm[t * SDIM + i], a);
        nq[t] = fmaxf(sqrtf(fmaxf(a, 0.0f)), 1e-12f);
    }
    __syncthreads();

    // chunks of 16 k-rows: G[q][k] and ||K_k||^2
    for (int kc = 0; kc < 128; kc += 16) {
        for (int idx = t; idx < 16 * SDIM; idx += 256) {
            int kk = idx / SDIM, j = idx - kk * SDIM;
            stage[kk * 145 + j] = g_Wk[h][kc + kk][j];
        }
        __syncthreads();
        {
            int q = t >> 4, kk = t & 15;
            float a = 0.0f;
            for (int i = 0; i < SDIM; i++)
                a = fmaf(Tt[q * SDIM + i], stage[kk * 145 + i], a);
            G[q * 128 + kc + kk] = a;
        }
        {
            int kk = t & 15, ig = t >> 4;
            float a = 0.0f;
            for (int i = ig * 9; i < ig * 9 + 9; i++) {
                float rd = 0.0f;
                for (int j = 0; j < SDIM; j++)
                    rd = fmaf(Sg[i * SDIM + j], stage[kk * 145 + j], rd);
                a = fmaf(stage[kk * 145 + i], rd, a);
            }
            red[t] = a;
        }
        __syncthreads();
        if (t < 16) {
            float sum = 0.0f;
            for (int g2 = 0; g2 < 16; g2++) sum += red[g2 * 16 + t];
            nk[kc + t] = fmaxf(sqrtf(fmaxf(sum, 0.0f)), 1e-12f);
        }
        __syncthreads();
    }

    // score = G / (|Q||K| sqrt(N)); sqrt(36864) = 192
    for (int idx = t; idx < 2048; idx += 256) {
        int q = idx >> 7, k = idx & 127;
        G[idx] = G[idx] / (nq[q] * nk[k] * 192.0f);
    }
    __syncthreads();

    // instance norm over 16x128
    float lsum = 0.0f;
    for (int idx = t; idx < 2048; idx += 256) lsum += G[idx];
    red[t] = lsum; __syncthreads();
    for (int st = 128; st > 0; st >>= 1) { if (t < st) red[t] += red[t + st]; __syncthreads(); }
    float mean = red[0] * (1.0f / 2048.0f);
    __syncthreads();
    float lss = 0.0f;
    for (int idx = t; idx < 2048; idx += 256) { float d = G[idx] - mean; lss = fmaf(d, d, lss); }
    red[t] = lss; __syncthreads();
    for (int st = 128; st > 0; st >>= 1) { if (t < st) red[t] += red[t + st]; __syncthreads(); }
    float var = red[0] * (1.0f / 2048.0f);
    float iscale = rsqrtf(var + 1e-5f);
    __syncthreads();
    for (int idx = t; idx < 2048; idx += 256)
        G[idx] = (G[idx] - mean) * iscale;
    __syncthreads();

    // softmax over k per row (8 warps x 2 rows)
    int wid = t >> 5, lane = t & 31;
    for (int q = wid; q < 16; q += 8) {
        float m = -1e30f;
        for (int k = lane; k < 128; k += 32) m = fmaxf(m, G[q * 128 + k]);
        #pragma unroll
        for (int o = 16; o > 0; o >>= 1) m = fmaxf(m, __shfl_xor_sync(0xffffffffu, m, o));
        float ssum = 0.0f;
        for (int k = lane; k < 128; k += 32) {
            float e = expf(G[q * 128 + k] - m);
            G[q * 128 + k] = e;
            ssum += e;
        }
        #pragma unroll
        for (int o = 16; o > 0; o >>= 1) ssum += __shfl_xor_sync(0xffffffffu, ssum, o);
        float inv = 1.0f / ssum;
        for (int k = lane; k < 128; k += 32) G[q * 128 + k] *= inv;
    }
    __syncthreads();

    // M[o][k] = sum_q w_out[o, h*16+q] attn[q][k]
    for (int idx = t; idx < OCH * 128; idx += 256) {
        int o = idx >> 7, k = idx & 127;
        float a = 0.0f;
        #pragma unroll
        for (int q = 0; q < 16; q++)
            a = fmaf(w_out[o * 64 + h * 16 + q], G[q * 128 + k], a);
        M[idx] = a;
    }
    __syncthreads();

    // Weff2[o][i] = sum_k M[o][k] Wv[k][i]
    for (int idx = t; idx < OCH * SDIM; idx += 256) {
        int o = idx / SDIM, i = idx - o * SDIM;
        float a = 0.0f;
        for (int k = 0; k < 128; k++)
            a = fmaf(M[o * 128 + k], g_Wv[h][k][i], a);
        g_W2[b][h][o][i] = a;
    }
}

// ---------------- kernel 5: fused output conv (4 dilated 3x3 convs) + BN stats ----------------
// grid (48 x-groups of 4 rows, Bb), 256 threads = 8 warps (o-groups of 4) x 32 lanes (y-groups of 6)
__global__ void __launch_bounds__(256) k_out(const float* __restrict__ cen, float* __restrict__ out) {
    extern __shared__ float dsm[];
    float* insm = dsm;                 // Cc*3*W2 = 10272 floats
    float* W2sm = dsm + Cc * 3 * W2;   // OCH*SDIM = 4608 floats

    int xg = blockIdx.x, b = blockIdx.y;
    int t = threadIdx.x;
    int ty = t & 31, to = t >> 5;
    const float* cb = cen + (size_t)b * Cc * NPIX;

    for (int xr = 0; xr < 4; xr++) {
        int x = xg * 4 + xr;
        float acc[4][6];
        #pragma unroll
        for (int oo = 0; oo < 4; oo++)
            #pragma unroll
            for (int j = 0; j < 6; j++) acc[oo][j] = 0.0f;

        for (int h = 0; h < Hh; h++) {
            int s = c_shift[h];
            int plen = HT + 2 * s;
            __syncthreads();
            for (int idx = t; idx < Cc * 3 * plen; idx += 256) {
                int c = idx / (3 * plen);
                int rem = idx - c * 3 * plen;
                int r = rem / plen;
                int p = rem - r * plen;
                int xx = x + (r - 1) * s;
                int y = p - s;
                float v = 0.0f;
                if (xx >= 0 && xx < WD && y >= 0 && y < HT)
                    v = cb[((size_t)c * WD + xx) * HT + y];
                insm[c * (3 * W2) + r * W2 + p] = v;
            }
            for (int idx = t; idx < OCH * SDIM; idx += 256)
                W2sm[idx] = (&g_W2[b][h][0][0])[idx];
            __syncthreads();

            int ybase = ty * 6;
            #pragma unroll 1
            for (int c = 0; c < Cc; c++) {
                const float* pc = insm + c * (3 * W2);
                #pragma unroll
                for (int d = 0; d < 9; d++) {
                    const float* px = pc + (d / 3) * W2 + (d % 3) * s + ybase;
                    float w0 = W2sm[(to * 4 + 0) * SDIM + c * 9 + d];
                    float w1 = W2sm[(to * 4 + 1) * SDIM + c * 9 + d];
                    float w2 = W2sm[(to * 4 + 2) * SDIM + c * 9 + d];
                    float w3 = W2sm[(to * 4 + 3) * SDIM + c * 9 + d];
                    #pragma unroll
                    for (int j = 0; j < 6; j++) {
                        float xv = px[j];
                        acc[0][j] = fmaf(w0, xv, acc[0][j]);
                        acc[1][j] = fmaf(w1, xv, acc[1][j]);
                        acc[2][j] = fmaf(w2, xv, acc[2][j]);
                        acc[3][j] = fmaf(w3, xv, acc[3][j]);
                    }
                }
            }
        }

        // write raw y + accumulate BN stats
        #pragma unroll
        for (int oo = 0; oo < 4; oo++) {
            int o = to * 4 + oo;
            float s1 = 0.0f, s2 = 0.0f;
            float* op = out + (((size_t)b * OCH + o) * WD + x) * HT + ty * 6;
            #pragma unroll
            for (int j = 0; j < 6; j++) {
                float v = acc[oo][j];
                op[j] = v;
                s1 += v;
                s2 = fmaf(v, v, s2);
            }
            #pragma unroll
            for (int off2 = 16; off2 > 0; off2 >>= 1) {
                s1 += __shfl_xor_sync(0xffffffffu, s1, off2);
                s2 += __shfl_xor_sync(0xffffffffu, s2, off2);
            }
            if (ty == 0) {
                atomicAdd(&g_bnsum[o], s1);
                atomicAdd(&g_bnsq[o], s2);
            }
        }
    }
}

// ---------------- kernel 6: batchnorm (train stats) + ReLU, in place ----------------
__global__ void k_bn(float* __restrict__ out, const float* __restrict__ gamma,
                     const float* __restrict__ beta) {
    __shared__ float ssc[OCH], sbi[OCH];
    if (threadIdx.x < OCH) {
        int o = threadIdx.x;
        float invN = 1.0f / ((float)Bb * NPIX);
        float m = g_bnsum[o] * invN;
        float v = g_bnsq[o] * invN - m * m;
        float sc = gamma[o] * rsqrtf(v + 1e-5f);
        ssc[o] = sc;
        sbi[o] = beta[o] - m * sc;
    }
    __syncthreads();
    size_t total = (size_t)Bb * OCH * NPIX;
    for (size_t i = (size_t)blockIdx.x * blockDim.x + threadIdx.x; i < total;
         i += (size_t)gridDim.x * blockDim.x) {
        int o = (int)((i / NPIX) & 31);
        float v = fmaf(out[i], ssc[o], sbi[o]);
        out[i] = fmaxf(v, 0.0f);
    }
}

// ---------------- launch ----------------
extern "C" void kernel_launch(void* const* d_in, const int* in_sizes, int n_in,
                              void* d_out, int out_size) {
    (void)in_sizes; (void)n_in; (void)out_size;
    const float* cen   = (const float*)d_in[0];
    const float* wq    = (const float*)d_in[1];
    const float* wk    = (const float*)d_in[2];
    const float* wv    = (const float*)d_in[3];
    const float* sum_w = (const float*)d_in[4];
    const float* w_out = (const float*)d_in[5];
    const float* gamma = (const float*)d_in[6];
    const float* beta  = (const float*)d_in[7];
    float* out = (float*)d_out;

    int dynsmem = (Cc * 3 * W2 + OCH * SDIM) * (int)sizeof(float);
    cudaFuncSetAttribute(k_out, cudaFuncAttributeMaxDynamicSharedMemorySize, dynsmem);

    k_prep<<<4, 256>>>(wq, wk, wv, sum_w);
    k_zero<<<1024, 256>>>();
    k_S<<<dim3(24, 4, 8), 256>>>(cen);
    k_attn<<<32, 256>>>(w_out);
    k_out<<<dim3(48, 8), 256, dynsmem>>>(cen, out);
    k_bn<<<2048, 256>>>(out, gamma, beta);
}